// round 16
// baseline (speedup 1.0000x reference)
#include <cuda_runtime.h>
#include <cuda_bf16.h>
#include <cstdint>

// Problem constants (fixed by reference setup_inputs)
#define B_    2
#define T_    2048
#define C_    1024
#define NHEAD 16
#define HSZ   64
#define W2S   2048   // w2 row stride (block_minus_1)

// ---- warp-level bf16 tensor-core MMA + ldmatrix (sm_80+ PTX) ----
__device__ __forceinline__ void mma_bf16(float* c, const uint32_t* a, const uint32_t* b) {
    asm volatile(
        "mma.sync.aligned.m16n8k16.row.col.f32.bf16.bf16.f32 "
        "{%0,%1,%2,%3}, {%4,%5,%6,%7}, {%8,%9}, {%0,%1,%2,%3};"
        : "+f"(c[0]), "+f"(c[1]), "+f"(c[2]), "+f"(c[3])
        : "r"(a[0]), "r"(a[1]), "r"(a[2]), "r"(a[3]), "r"(b[0]), "r"(b[1]));
}
#define LDSM_X4(r, addr) \
    asm volatile("ldmatrix.sync.aligned.m8n8.x4.shared.b16 {%0,%1,%2,%3}, [%4];" \
        : "=r"((r)[0]), "=r"((r)[1]), "=r"((r)[2]), "=r"((r)[3]) : "r"(addr))

__device__ __forceinline__ uint32_t smem_u32(const void* p) {
    uint32_t a;
    asm("{ .reg .u64 t; cvta.to.shared.u64 t, %1; cvt.u32.u64 %0, t; }" : "=r"(a) : "l"(p));
    return a;
}

// Scratch (allocation-free rule: __device__ globals)
__device__ float g_R[B_*T_*C_];   // relu(x @ W1^T + b1), (B*T, C) layout
__device__ float g_V[B_*T_*C_];   // x @ Wv^T + bv
__device__ float g_Y[B_*T_*C_];   // attention output, (B*T, C)

// ---------------------------------------------------------------------------
// Tensor-core GEMM via mma.sync (HMMA). CTA 128x128, K-tile 64, bf16 hi/lo
// split (3 MMAs: ah*wh + ah*wl + al*wh). OCC-1 + register prefetch (R14,
// 82.9us proven) + DOUBLE-BUFFERED smem: STS(tile it+1) and MMA(tile it) run
// in the same barrier interval on different buffers, so warps overlap the
// convert/STS phase with tensor work instead of serializing at a barrier.
// ---------------------------------------------------------------------------
#define SP     72                     // smem row stride in bf16 elements
#define GT_KT  64
#define BUF_E  (4 * 128 * SP)         // bf16 elements per buffer (Ah,Al,Wh,Wl)
#define GT_SMEM (2 * BUF_E * 2)       // 147456 B (double buffer), occ 1

__global__ __launch_bounds__(256, 1)
void gemm_hmma(const float* __restrict__ A, const float* __restrict__ W,
               const float* __restrict__ bias, float* __restrict__ out,
               int M, int N, int K, int relu)
{
    extern __shared__ __align__(16) char smem[];
    __nv_bfloat16* base_bf = (__nv_bfloat16*)smem;

    const int tid  = threadIdx.x;
    const int wid  = tid >> 5, lane = tid & 31;
    const int g    = lane >> 2, t = lane & 3;
    const int wm0  = (wid & 3) * 32;
    const int wn0  = (wid >> 2) * 64;
    const int m0   = blockIdx.y * 128, n0 = blockIdx.x * 128;

    const uint32_t a_off = ((uint32_t)(wm0 + (lane & 15)) * SP + (uint32_t)((lane >> 4) << 3)) * 2u;
    const uint32_t b_off = (((uint32_t)(wn0 + (lane & 7) + ((lane >> 4) << 3))) * SP
                          + (uint32_t)(((lane >> 3) & 1) << 3)) * 2u;
    const uint32_t sm_b = smem_u32(base_bf);
    // byte offsets of the four sub-tiles inside a buffer
    const uint32_t AH_O = 0, AL_O = 128 * SP * 2, WH_O = 2 * 128 * SP * 2, WL_O = 3 * 128 * SP * 2;
    const uint32_t BUF_B = BUF_E * 2;  // buffer stride in bytes

    const int trow = tid >> 4;
    const int tcol = (tid & 15) << 2;

    float acc[2][8][4];
    #pragma unroll
    for (int mt = 0; mt < 2; mt++)
        #pragma unroll
        for (int nt = 0; nt < 8; nt++)
            #pragma unroll
            for (int r = 0; r < 4; r++) acc[mt][nt][r] = 0.f;

    // convert+STS of the prefetched registers into buffer `buf`
    auto stage = [&](const float4* av, const float4* wv, int buf) {
        __nv_bfloat16* Ah = base_bf + buf * BUF_E;
        __nv_bfloat16* Al = Ah + 128 * SP;
        __nv_bfloat16* Wh = Al + 128 * SP;
        __nv_bfloat16* Wl = Wh + 128 * SP;
        #pragma unroll
        for (int p = 0; p < 8; p++) {
            const int r = trow + p * 16;
            const int eo = r * SP + tcol;
            __nv_bfloat162 h01 = __floats2bfloat162_rn(av[p].x, av[p].y);
            __nv_bfloat162 h23 = __floats2bfloat162_rn(av[p].z, av[p].w);
            __nv_bfloat162 l01 = __floats2bfloat162_rn(av[p].x - __bfloat162float(h01.x),
                                                       av[p].y - __bfloat162float(h01.y));
            __nv_bfloat162 l23 = __floats2bfloat162_rn(av[p].z - __bfloat162float(h23.x),
                                                       av[p].w - __bfloat162float(h23.y));
            *(uint2*)(Ah + eo) = make_uint2(*(uint32_t*)&h01, *(uint32_t*)&h23);
            *(uint2*)(Al + eo) = make_uint2(*(uint32_t*)&l01, *(uint32_t*)&l23);
            h01 = __floats2bfloat162_rn(wv[p].x, wv[p].y);
            h23 = __floats2bfloat162_rn(wv[p].z, wv[p].w);
            l01 = __floats2bfloat162_rn(wv[p].x - __bfloat162float(h01.x),
                                        wv[p].y - __bfloat162float(h01.y));
            l23 = __floats2bfloat162_rn(wv[p].z - __bfloat162float(h23.x),
                                        wv[p].w - __bfloat162float(h23.y));
            *(uint2*)(Wh + eo) = make_uint2(*(uint32_t*)&h01, *(uint32_t*)&h23);
            *(uint2*)(Wl + eo) = make_uint2(*(uint32_t*)&l01, *(uint32_t*)&l23);
        }
    };

    float4 av[8], wv[8];
    // prologue: LDG tile0, stage into buf0, LDG tile1
    #pragma unroll
    for (int p = 0; p < 8; p++) {
        const int r = trow + p * 16;
        av[p] = *(const float4*)(A + (size_t)(m0 + r) * K + tcol);
        wv[p] = *(const float4*)(W + (size_t)(n0 + r) * K + tcol);
    }
    stage(av, wv, 0);
    #pragma unroll
    for (int p = 0; p < 8; p++) {
        const int r = trow + p * 16;
        av[p] = *(const float4*)(A + (size_t)(m0 + r) * K + GT_KT + tcol);
        wv[p] = *(const float4*)(W + (size_t)(n0 + r) * K + GT_KT + tcol);
    }
    __syncthreads();

    const int NT = K / GT_KT;                  // 16
    for (int it = 0; it < NT; it++) {
        const int cur = it & 1, nxt = cur ^ 1;
        // STS tile it+1 into the other buffer (no barrier before MMA below)
        if (it + 1 < NT) stage(av, wv, nxt);
        // LDG tile it+2 (latency hidden by MMAs)
        if (it + 2 < NT) {
            const int kt = (it + 2) * GT_KT;
            #pragma unroll
            for (int p = 0; p < 8; p++) {
                const int r = trow + p * 16;
                av[p] = *(const float4*)(A + (size_t)(m0 + r) * K + kt + tcol);
                wv[p] = *(const float4*)(W + (size_t)(n0 + r) * K + kt + tcol);
            }
        }
        // MMA tile it from buffer cur
        const uint32_t bb = sm_b + (uint32_t)cur * BUF_B;
        #pragma unroll
        for (int ks = 0; ks < 4; ks++) {
            const uint32_t kb = (uint32_t)(ks * 16) * 2u;
            uint32_t afh[2][4], afl[2][4];
            #pragma unroll
            for (int mt = 0; mt < 2; mt++) {
                const uint32_t ro = (uint32_t)(mt * 16 * SP) * 2u + a_off + kb;
                LDSM_X4(afh[mt], bb + AH_O + ro);
                LDSM_X4(afl[mt], bb + AL_O + ro);
            }
            #pragma unroll
            for (int np = 0; np < 4; np++) {
                const uint32_t ro = (uint32_t)(np * 16 * SP) * 2u + b_off + kb;
                uint32_t rh[4], rl[4];
                LDSM_X4(rh, bb + WH_O + ro);
                LDSM_X4(rl, bb + WL_O + ro);
                uint32_t bh0[2] = {rh[0], rh[1]}, bh1[2] = {rh[2], rh[3]};
                uint32_t bl0[2] = {rl[0], rl[1]}, bl1[2] = {rl[2], rl[3]};
                #pragma unroll
                for (int mt = 0; mt < 2; mt++) {
                    mma_bf16(acc[mt][2*np],   afh[mt], bh0);
                    mma_bf16(acc[mt][2*np],   afh[mt], bl0);
                    mma_bf16(acc[mt][2*np],   afl[mt], bh0);
                    mma_bf16(acc[mt][2*np+1], afh[mt], bh1);
                    mma_bf16(acc[mt][2*np+1], afh[mt], bl1);
                    mma_bf16(acc[mt][2*np+1], afl[mt], bh1);
                }
            }
        }
        // one barrier per tile: publishes STS(nxt) for next iter's MMA and
        // protects buf cur from being overwritten before all MMA reads done
        __syncthreads();
    }

    #pragma unroll
    for (int mt = 0; mt < 2; mt++) {
        const int row0 = m0 + wm0 + mt * 16 + g;
        #pragma unroll
        for (int nt = 0; nt < 8; nt++) {
            const int col = n0 + wn0 + nt * 8 + t * 2;
            const float b0 = bias[col], b1 = bias[col + 1];
            float v0 = acc[mt][nt][0] + b0, v1 = acc[mt][nt][1] + b1;
            float v2 = acc[mt][nt][2] + b0, v3 = acc[mt][nt][3] + b1;
            if (relu) {
                v0 = fmaxf(v0, 0.f); v1 = fmaxf(v1, 0.f);
                v2 = fmaxf(v2, 0.f); v3 = fmaxf(v3, 0.f);
            }
            *(float2*)(out + (size_t)row0 * N + col)       = make_float2(v0, v1);
            *(float2*)(out + (size_t)(row0 + 8) * N + col) = make_float2(v2, v3);
        }
    }
}

// ---------------------------------------------------------------------------
// Tensor-core fused causal synthesizer attention (FlashAttention-2 style).
// OCC-2 version — unchanged from R15 (measured ~27us better than occ-1).
// ---------------------------------------------------------------------------
#define ASP 72   // bf16 row stride (144 B)

__global__ __launch_bounds__(256, 2)
void synth_attn_tc(const float* __restrict__ R, const float* __restrict__ V,
                   const float* __restrict__ w2, const float* __restrict__ b2,
                   float* __restrict__ Y)
{
    extern __shared__ __align__(16) char smem[];
    __nv_bfloat16* Rh_s  = (__nv_bfloat16*)smem;       // [128][ASP]
    __nv_bfloat16* W2t_s = Rh_s + 128 * ASP;           // [64][ASP]  rows j, cols d
    __nv_bfloat16* Vth_s = W2t_s + 64 * ASP;           // [64][ASP]  rows hd, cols j
    __nv_bfloat16* Vtl_s = Vth_s + 64 * ASP;           // [64][ASP]
    float*         b2_s  = (float*)(Vtl_s + 64 * ASP); // [64]

    const int tid = threadIdx.x;
    const int wid = tid >> 5, lane = tid & 31;
    const int g = lane >> 2, t = lane & 3;
    const int wm = wid * 16;                           // warp's t-row block
    const int t0 = ((int)gridDim.x - 1 - (int)blockIdx.x) * 128;
    const int h = blockIdx.y, b = blockIdx.z;

    const uint32_t rh_b  = smem_u32(Rh_s);
    const uint32_t w2t_b = smem_u32(W2t_s);
    const uint32_t vth_b = smem_u32(Vth_s);
    const uint32_t vtl_b = smem_u32(Vtl_s);

    const uint32_t a_off = ((uint32_t)(wm + (lane & 15)) * ASP + ((lane >> 4) << 3)) * 2u;
    const uint32_t b_off = (((uint32_t)((lane & 7) + ((lane >> 4) << 3))) * ASP
                          + (((lane >> 3) & 1) << 3)) * 2u;

    // ---- stage R tile (128x64 fp32 -> bf16, natural layout) ----
    const float* Rbase = R + ((size_t)b * T_ + t0) * C_ + h * HSZ;
    {
        const int rr = tid >> 4;
        const int c4 = (tid & 15) << 2;
        #pragma unroll
        for (int p = 0; p < 8; p++) {
            const int r = rr + p * 16;
            float4 v = *(const float4*)(Rbase + (size_t)r * C_ + c4);
            __nv_bfloat162 h01 = __floats2bfloat162_rn(v.x, v.y);
            __nv_bfloat162 h23 = __floats2bfloat162_rn(v.z, v.w);
            *(uint2*)(Rh_s + r * ASP + c4) = make_uint2(*(uint32_t*)&h01, *(uint32_t*)&h23);
        }
    }

    float O[8][4];
    #pragma unroll
    for (int nt = 0; nt < 8; nt++)
        #pragma unroll
        for (int r = 0; r < 4; r++) O[nt][r] = 0.f;
    float rs0 = 0.f, rs1 = 0.f;

    const float* Vbase = V + (size_t)b * T_ * C_ + h * HSZ;

    // transpose-staging map: out elem (row = sx+16e, col = sj*4+q)
    const int sx = tid & 15, sj = tid >> 4;

    const int jend = t0 + 128;
    for (int j0 = 0; j0 < jend; j0 += 64) {
        __syncthreads();   // previous PV MMAs done reading W2t/Vt
        #pragma unroll
        for (int e = 0; e < 4; e++) {
            const int orow = sx + 16*e;
            #pragma unroll
            for (int q = 0; q < 4; q++) {
                const int d = sj*4 + q;
                const int oidx = orow * ASP + d;
                const float wv = w2[(size_t)d * W2S + j0 + orow];
                W2t_s[oidx] = __float2bfloat16(wv);
                const float v = Vbase[(size_t)(j0 + d) * C_ + orow];
                const __nv_bfloat16 vh = __float2bfloat16(v);
                Vth_s[oidx] = vh;
                Vtl_s[oidx] = __float2bfloat16(v - __bfloat162float(vh));
            }
        }
        if (tid < 64) b2_s[tid] = b2[j0 + tid];
        __syncthreads();

        // ---- S = Rh @ W2t^T ----
        float S[8][4];
        #pragma unroll
        for (int nt = 0; nt < 8; nt++) { S[nt][0]=0.f; S[nt][1]=0.f; S[nt][2]=0.f; S[nt][3]=0.f; }
        #pragma unroll
        for (int ks = 0; ks < 4; ks++) {
            uint32_t af[4];
            LDSM_X4(af, rh_b + a_off + (uint32_t)(ks * 32));
            #pragma unroll
            for (int np = 0; np < 4; np++) {
                uint32_t bf[4];
                LDSM_X4(bf, w2t_b + b_off + (uint32_t)(np * 16 * ASP * 2 + ks * 32));
                uint32_t b0[2] = {bf[0], bf[1]}, b1[2] = {bf[2], bf[3]};
                mma_bf16(S[2*np],   af, b0);
                mma_bf16(S[2*np+1], af, b1);
            }
        }

        // ---- mask + b2 + exp + rowsum + repack P into A-fragments ----
        const bool diag = (j0 + 64 > t0);
        const int trow0 = t0 + wm + g, trow1 = trow0 + 8;
        uint32_t ph[4][4], pl[4][4];
        #pragma unroll
        for (int nt = 0; nt < 8; nt++) {
            const int col = nt*8 + 2*t;
            const float bb0 = b2_s[col], bb1 = b2_s[col+1];
            float s0 = S[nt][0] + bb0, s1 = S[nt][1] + bb1;
            float s2 = S[nt][2] + bb0, s3 = S[nt][3] + bb1;
            if (diag) {
                const int jg = j0 + col;
                if (jg     > trow0) s0 = -1e30f;
                if (jg + 1 > trow0) s1 = -1e30f;
                if (jg     > trow1) s2 = -1e30f;
                if (jg + 1 > trow1) s3 = -1e30f;
            }
            const float p0 = __expf(s0), p1 = __expf(s1);
            const float p2 = __expf(s2), p3 = __expf(s3);
            rs0 += p0 + p1; rs1 += p2 + p3;
            __nv_bfloat162 h01 = __floats2bfloat162_rn(p0, p1);
            __nv_bfloat162 h23 = __floats2bfloat162_rn(p2, p3);
            __nv_bfloat162 l01 = __floats2bfloat162_rn(p0 - __bfloat162float(h01.x),
                                                       p1 - __bfloat162float(h01.y));
            __nv_bfloat162 l23 = __floats2bfloat162_rn(p2 - __bfloat162float(h23.x),
                                                       p3 - __bfloat162float(h23.y));
            const int ks = nt >> 1, half = (nt & 1) << 1;
            ph[ks][half]     = *(uint32_t*)&h01;           // row g
            ph[ks][half + 1] = *(uint32_t*)&h23;           // row g+8
            pl[ks][half]     = *(uint32_t*)&l01;
            pl[ks][half + 1] = *(uint32_t*)&l23;
        }

        // ---- O += (Ph+Pl) @ (Vth+Vtl)^T  (drop Pl*Vtl, ~1.6e-5 rel) ----
        #pragma unroll
        for (int ks = 0; ks < 4; ks++) {
            #pragma unroll
            for (int np = 0; np < 4; np++) {
                const uint32_t ro = b_off + (uint32_t)(np * 16 * ASP * 2 + ks * 32);
                uint32_t bh[4], bl[4];
                LDSM_X4(bh, vth_b + ro);
                LDSM_X4(bl, vtl_b + ro);
                uint32_t bh0[2]={bh[0],bh[1]}, bh1[2]={bh[2],bh[3]};
                uint32_t bl0[2]={bl[0],bl[1]}, bl1[2]={bl[2],bl[3]};
                mma_bf16(O[2*np],   ph[ks], bh0);
                mma_bf16(O[2*np],   ph[ks], bl0);
                mma_bf16(O[2*np],   pl[ks], bh0);
                mma_bf16(O[2*np+1], ph[ks], bh1);
                mma_bf16(O[2*np+1], ph[ks], bl1);
                mma_bf16(O[2*np+1], pl[ks], bh1);
            }
        }
    }

    // quad-reduce row sums, normalize, store
    rs0 += __shfl_xor_sync(0xffffffffu, rs0, 1);
    rs0 += __shfl_xor_sync(0xffffffffu, rs0, 2);
    rs1 += __shfl_xor_sync(0xffffffffu, rs1, 1);
    rs1 += __shfl_xor_sync(0xffffffffu, rs1, 2);
    const float i0 = 1.f / rs0, i1 = 1.f / rs1;
    float* Ybase = Y + ((size_t)b * T_ + t0) * C_ + h * HSZ;
    #pragma unroll
    for (int nt = 0; nt < 8; nt++) {
        const int c = nt*8 + 2*t;
        *(float2*)(Ybase + (size_t)(wm + g) * C_ + c) =
            make_float2(O[nt][0] * i0, O[nt][1] * i0);
        *(float2*)(Ybase + (size_t)(wm + g + 8) * C_ + c) =
            make_float2(O[nt][2] * i1, O[nt][3] * i1);
    }
}

#define AT_SMEM ((128 + 3*64) * ASP * 2 + 64 * 4)   // 46336 B (x2 CTAs = 92.7KB)

// ---------------------------------------------------------------------------
extern "C" void kernel_launch(void* const* d_in, const int* in_sizes, int n_in,
                              void* d_out, int out_size)
{
    const float* x  = (const float*)d_in[0];
    const float* W1 = (const float*)d_in[1];
    const float* b1 = (const float*)d_in[2];
    const float* w2 = (const float*)d_in[3];
    const float* b2 = (const float*)d_in[4];
    const float* Wv = (const float*)d_in[5];
    const float* bv = (const float*)d_in[6];
    const float* Wp = (const float*)d_in[7];
    const float* bp = (const float*)d_in[8];
    float* out = (float*)d_out;

    float *Rp, *Vp, *Yp;
    cudaGetSymbolAddress((void**)&Rp, g_R);
    cudaGetSymbolAddress((void**)&Vp, g_V);
    cudaGetSymbolAddress((void**)&Yp, g_Y);

    const int M = B_ * T_;  // 4096
    dim3 gg(C_ / 128, M / 128);             // (8, 32)

    cudaFuncSetAttribute((const void*)gemm_hmma,
                         cudaFuncAttributeMaxDynamicSharedMemorySize, GT_SMEM);
    cudaFuncSetAttribute((const void*)synth_attn_tc,
                         cudaFuncAttributeMaxDynamicSharedMemorySize, AT_SMEM);

    gemm_hmma<<<gg, 256, GT_SMEM>>>(x, W1, b1, Rp, M, C_, C_, 1);   // R = relu(x W1^T + b1)
    gemm_hmma<<<gg, 256, GT_SMEM>>>(x, Wv, bv, Vp, M, C_, C_, 0);   // V = x Wv^T + bv

    dim3 ga(T_ / 128, NHEAD, B_);           // (16, 16, 2)
    synth_attn_tc<<<ga, 256, AT_SMEM>>>(Rp, Vp, w2, b2, Yp);

    gemm_hmma<<<gg, 256, GT_SMEM>>>(Yp, Wp, bp, out, M, C_, C_, 0); // out = Y Wp^T + bp
}

// round 17
// speedup vs baseline: 1.0142x; 1.0142x over previous
#include <cuda_runtime.h>
#include <cuda_bf16.h>
#include <cstdint>

// Problem constants (fixed by reference setup_inputs)
#define B_    2
#define T_    2048
#define C_    1024
#define NHEAD 16
#define HSZ   64
#define W2S   2048   // w2 row stride (block_minus_1)

// ---- warp-level bf16 tensor-core MMA + ldmatrix (sm_80+ PTX) ----
__device__ __forceinline__ void mma_bf16(float* c, const uint32_t* a, const uint32_t* b) {
    asm volatile(
        "mma.sync.aligned.m16n8k16.row.col.f32.bf16.bf16.f32 "
        "{%0,%1,%2,%3}, {%4,%5,%6,%7}, {%8,%9}, {%0,%1,%2,%3};"
        : "+f"(c[0]), "+f"(c[1]), "+f"(c[2]), "+f"(c[3])
        : "r"(a[0]), "r"(a[1]), "r"(a[2]), "r"(a[3]), "r"(b[0]), "r"(b[1]));
}
#define LDSM_X4(r, addr) \
    asm volatile("ldmatrix.sync.aligned.m8n8.x4.shared.b16 {%0,%1,%2,%3}, [%4];" \
        : "=r"((r)[0]), "=r"((r)[1]), "=r"((r)[2]), "=r"((r)[3]) : "r"(addr))

__device__ __forceinline__ uint32_t smem_u32(const void* p) {
    uint32_t a;
    asm("{ .reg .u64 t; cvta.to.shared.u64 t, %1; cvt.u32.u64 %0, t; }" : "=r"(a) : "l"(p));
    return a;
}

// Scratch (allocation-free rule: __device__ globals)
__device__ float g_R[B_*T_*C_];   // relu(x @ W1^T + b1), (B*T, C) layout
__device__ float g_V[B_*T_*C_];   // x @ Wv^T + bv
__device__ float g_Y[B_*T_*C_];   // attention output, (B*T, C)

// ---------------------------------------------------------------------------
// Tensor-core GEMM via mma.sync (HMMA). R14 structure (occ-1, single smem
// buffer, register prefetch of next k-tile) + TERM-MAJOR MMA ordering:
// each accumulator is touched once per term pass, so same-acc MMA distance
// is 16 (was 3 back-to-back RAW-dependent MMAs -> latency-bound issue).
// Per-acc term order (hh, hl, lh) is preserved -> numerics identical.
// ---------------------------------------------------------------------------
#define SP   72                    // smem row stride in bf16 elements
#define GT_KT 64
#define GT_SMEM (4 * 128 * SP * 2) // Ah, Al, Wh, Wl: 73728 B

__global__ __launch_bounds__(256, 1)
void gemm_hmma(const float* __restrict__ A, const float* __restrict__ W,
               const float* __restrict__ bias, float* __restrict__ out,
               int M, int N, int K, int relu)
{
    extern __shared__ __align__(16) char smem[];
    __nv_bfloat16* Ah = (__nv_bfloat16*)smem;
    __nv_bfloat16* Al = Ah + 128 * SP;
    __nv_bfloat16* Wh = Al + 128 * SP;
    __nv_bfloat16* Wl = Wh + 128 * SP;

    const int tid  = threadIdx.x;
    const int wid  = tid >> 5, lane = tid & 31;
    const int g    = lane >> 2, t = lane & 3;
    const int wm0  = (wid & 3) * 32;
    const int wn0  = (wid >> 2) * 64;
    const int m0   = blockIdx.y * 128, n0 = blockIdx.x * 128;

    const uint32_t a_off = ((uint32_t)(wm0 + (lane & 15)) * SP + (uint32_t)((lane >> 4) << 3)) * 2u;
    const uint32_t b_off = (((uint32_t)(wn0 + (lane & 7) + ((lane >> 4) << 3))) * SP
                          + (uint32_t)(((lane >> 3) & 1) << 3)) * 2u;

    const uint32_t ah_b = smem_u32(Ah), al_b = smem_u32(Al);
    const uint32_t wh_b = smem_u32(Wh), wl_b = smem_u32(Wl);

    const int trow = tid >> 4;
    const int tcol = (tid & 15) << 2;

    float acc[2][8][4];
    #pragma unroll
    for (int mt = 0; mt < 2; mt++)
        #pragma unroll
        for (int nt = 0; nt < 8; nt++)
            #pragma unroll
            for (int r = 0; r < 4; r++) acc[mt][nt][r] = 0.f;

    float4 av[8], wv[8];
    #pragma unroll
    for (int p = 0; p < 8; p++) {
        const int r = trow + p * 16;
        av[p] = *(const float4*)(A + (size_t)(m0 + r) * K + tcol);
        wv[p] = *(const float4*)(W + (size_t)(n0 + r) * K + tcol);
    }

    const int NT = K / GT_KT;
    for (int it = 0; it < NT; it++) {
        if (it > 0) __syncthreads();
        #pragma unroll
        for (int p = 0; p < 8; p++) {
            const int r = trow + p * 16;
            const int eo = r * SP + tcol;
            __nv_bfloat162 h01 = __floats2bfloat162_rn(av[p].x, av[p].y);
            __nv_bfloat162 h23 = __floats2bfloat162_rn(av[p].z, av[p].w);
            __nv_bfloat162 l01 = __floats2bfloat162_rn(av[p].x - __bfloat162float(h01.x),
                                                       av[p].y - __bfloat162float(h01.y));
            __nv_bfloat162 l23 = __floats2bfloat162_rn(av[p].z - __bfloat162float(h23.x),
                                                       av[p].w - __bfloat162float(h23.y));
            *(uint2*)(Ah + eo) = make_uint2(*(uint32_t*)&h01, *(uint32_t*)&h23);
            *(uint2*)(Al + eo) = make_uint2(*(uint32_t*)&l01, *(uint32_t*)&l23);
            h01 = __floats2bfloat162_rn(wv[p].x, wv[p].y);
            h23 = __floats2bfloat162_rn(wv[p].z, wv[p].w);
            l01 = __floats2bfloat162_rn(wv[p].x - __bfloat162float(h01.x),
                                        wv[p].y - __bfloat162float(h01.y));
            l23 = __floats2bfloat162_rn(wv[p].z - __bfloat162float(h23.x),
                                        wv[p].w - __bfloat162float(h23.y));
            *(uint2*)(Wh + eo) = make_uint2(*(uint32_t*)&h01, *(uint32_t*)&h23);
            *(uint2*)(Wl + eo) = make_uint2(*(uint32_t*)&l01, *(uint32_t*)&l23);
        }
        __syncthreads();
        if (it + 1 < NT) {
            const int kt = (it + 1) * GT_KT;
            #pragma unroll
            for (int p = 0; p < 8; p++) {
                const int r = trow + p * 16;
                av[p] = *(const float4*)(A + (size_t)(m0 + r) * K + kt + tcol);
                wv[p] = *(const float4*)(W + (size_t)(n0 + r) * K + kt + tcol);
            }
        }
        #pragma unroll
        for (int ks = 0; ks < 4; ks++) {
            const uint32_t kb = (uint32_t)(ks * 16) * 2u;
            uint32_t afh[2][4], afl[2][4];
            #pragma unroll
            for (int mt = 0; mt < 2; mt++) {
                const uint32_t ro = (uint32_t)(mt * 16 * SP) * 2u + a_off + kb;
                LDSM_X4(afh[mt], ah_b + ro);
                LDSM_X4(afl[mt], al_b + ro);
            }
            uint32_t bfh[8][2], bfl[8][2];
            #pragma unroll
            for (int np = 0; np < 4; np++) {
                const uint32_t ro = (uint32_t)(np * 16 * SP) * 2u + b_off + kb;
                uint32_t rh[4], rl[4];
                LDSM_X4(rh, wh_b + ro);
                LDSM_X4(rl, wl_b + ro);
                bfh[2*np][0]   = rh[0]; bfh[2*np][1]   = rh[1];
                bfh[2*np+1][0] = rh[2]; bfh[2*np+1][1] = rh[3];
                bfl[2*np][0]   = rl[0]; bfl[2*np][1]   = rl[1];
                bfl[2*np+1][0] = rl[2]; bfl[2*np+1][1] = rl[3];
            }
            // TERM-MAJOR: pass 1 = ah*wh, pass 2 = ah*wl, pass 3 = al*wh.
            // Same-accumulator distance = 16 MMAs (covers HMMA latency).
            #pragma unroll
            for (int nt = 0; nt < 8; nt++)
                #pragma unroll
                for (int mt = 0; mt < 2; mt++)
                    mma_bf16(acc[mt][nt], afh[mt], bfh[nt]);
            #pragma unroll
            for (int nt = 0; nt < 8; nt++)
                #pragma unroll
                for (int mt = 0; mt < 2; mt++)
                    mma_bf16(acc[mt][nt], afh[mt], bfl[nt]);
            #pragma unroll
            for (int nt = 0; nt < 8; nt++)
                #pragma unroll
                for (int mt = 0; mt < 2; mt++)
                    mma_bf16(acc[mt][nt], afl[mt], bfh[nt]);
        }
    }

    #pragma unroll
    for (int mt = 0; mt < 2; mt++) {
        const int row0 = m0 + wm0 + mt * 16 + g;
        #pragma unroll
        for (int nt = 0; nt < 8; nt++) {
            const int col = n0 + wn0 + nt * 8 + t * 2;
            const float b0 = bias[col], b1 = bias[col + 1];
            float v0 = acc[mt][nt][0] + b0, v1 = acc[mt][nt][1] + b1;
            float v2 = acc[mt][nt][2] + b0, v3 = acc[mt][nt][3] + b1;
            if (relu) {
                v0 = fmaxf(v0, 0.f); v1 = fmaxf(v1, 0.f);
                v2 = fmaxf(v2, 0.f); v3 = fmaxf(v3, 0.f);
            }
            *(float2*)(out + (size_t)row0 * N + col)       = make_float2(v0, v1);
            *(float2*)(out + (size_t)(row0 + 8) * N + col) = make_float2(v2, v3);
        }
    }
}

// ---------------------------------------------------------------------------
// Tensor-core fused causal synthesizer attention (FlashAttention-2 style).
// OCC-2 (R15, proven) + PV MMAs in 2-np batches with term-major ordering:
// same-O accumulator distance 4 (was 3 back-to-back RAW-dependent MMAs).
// Per-acc term order (ph*vh, ph*vl, pl*vh) preserved -> numerics identical.
// ---------------------------------------------------------------------------
#define ASP 72   // bf16 row stride (144 B)

__global__ __launch_bounds__(256, 2)
void synth_attn_tc(const float* __restrict__ R, const float* __restrict__ V,
                   const float* __restrict__ w2, const float* __restrict__ b2,
                   float* __restrict__ Y)
{
    extern __shared__ __align__(16) char smem[];
    __nv_bfloat16* Rh_s  = (__nv_bfloat16*)smem;       // [128][ASP]
    __nv_bfloat16* W2t_s = Rh_s + 128 * ASP;           // [64][ASP]  rows j, cols d
    __nv_bfloat16* Vth_s = W2t_s + 64 * ASP;           // [64][ASP]  rows hd, cols j
    __nv_bfloat16* Vtl_s = Vth_s + 64 * ASP;           // [64][ASP]
    float*         b2_s  = (float*)(Vtl_s + 64 * ASP); // [64]

    const int tid = threadIdx.x;
    const int wid = tid >> 5, lane = tid & 31;
    const int g = lane >> 2, t = lane & 3;
    const int wm = wid * 16;                           // warp's t-row block
    const int t0 = ((int)gridDim.x - 1 - (int)blockIdx.x) * 128;
    const int h = blockIdx.y, b = blockIdx.z;

    const uint32_t rh_b  = smem_u32(Rh_s);
    const uint32_t w2t_b = smem_u32(W2t_s);
    const uint32_t vth_b = smem_u32(Vth_s);
    const uint32_t vtl_b = smem_u32(Vtl_s);

    const uint32_t a_off = ((uint32_t)(wm + (lane & 15)) * ASP + ((lane >> 4) << 3)) * 2u;
    const uint32_t b_off = (((uint32_t)((lane & 7) + ((lane >> 4) << 3))) * ASP
                          + (((lane >> 3) & 1) << 3)) * 2u;

    // ---- stage R tile (128x64 fp32 -> bf16, natural layout) ----
    const float* Rbase = R + ((size_t)b * T_ + t0) * C_ + h * HSZ;
    {
        const int rr = tid >> 4;
        const int c4 = (tid & 15) << 2;
        #pragma unroll
        for (int p = 0; p < 8; p++) {
            const int r = rr + p * 16;
            float4 v = *(const float4*)(Rbase + (size_t)r * C_ + c4);
            __nv_bfloat162 h01 = __floats2bfloat162_rn(v.x, v.y);
            __nv_bfloat162 h23 = __floats2bfloat162_rn(v.z, v.w);
            *(uint2*)(Rh_s + r * ASP + c4) = make_uint2(*(uint32_t*)&h01, *(uint32_t*)&h23);
        }
    }

    float O[8][4];
    #pragma unroll
    for (int nt = 0; nt < 8; nt++)
        #pragma unroll
        for (int r = 0; r < 4; r++) O[nt][r] = 0.f;
    float rs0 = 0.f, rs1 = 0.f;

    const float* Vbase = V + (size_t)b * T_ * C_ + h * HSZ;

    // transpose-staging map: out elem (row = sx+16e, col = sj*4+q)
    const int sx = tid & 15, sj = tid >> 4;

    const int jend = t0 + 128;
    for (int j0 = 0; j0 < jend; j0 += 64) {
        __syncthreads();   // previous PV MMAs done reading W2t/Vt
        #pragma unroll
        for (int e = 0; e < 4; e++) {
            const int orow = sx + 16*e;
            #pragma unroll
            for (int q = 0; q < 4; q++) {
                const int d = sj*4 + q;
                const int oidx = orow * ASP + d;
                const float wvv = w2[(size_t)d * W2S + j0 + orow];
                W2t_s[oidx] = __float2bfloat16(wvv);
                const float v = Vbase[(size_t)(j0 + d) * C_ + orow];
                const __nv_bfloat16 vh = __float2bfloat16(v);
                Vth_s[oidx] = vh;
                Vtl_s[oidx] = __float2bfloat16(v - __bfloat162float(vh));
            }
        }
        if (tid < 64) b2_s[tid] = b2[j0 + tid];
        __syncthreads();

        // ---- S = Rh @ W2t^T ----
        float S[8][4];
        #pragma unroll
        for (int nt = 0; nt < 8; nt++) { S[nt][0]=0.f; S[nt][1]=0.f; S[nt][2]=0.f; S[nt][3]=0.f; }
        #pragma unroll
        for (int ks = 0; ks < 4; ks++) {
            uint32_t af[4];
            LDSM_X4(af, rh_b + a_off + (uint32_t)(ks * 32));
            #pragma unroll
            for (int np = 0; np < 4; np++) {
                uint32_t bf[4];
                LDSM_X4(bf, w2t_b + b_off + (uint32_t)(np * 16 * ASP * 2 + ks * 32));
                uint32_t b0[2] = {bf[0], bf[1]}, b1[2] = {bf[2], bf[3]};
                mma_bf16(S[2*np],   af, b0);
                mma_bf16(S[2*np+1], af, b1);
            }
        }

        // ---- mask + b2 + exp + rowsum + repack P into A-fragments ----
        const bool diag = (j0 + 64 > t0);
        const int trow0 = t0 + wm + g, trow1 = trow0 + 8;
        uint32_t ph[4][4], pl[4][4];
        #pragma unroll
        for (int nt = 0; nt < 8; nt++) {
            const int col = nt*8 + 2*t;
            const float bb0 = b2_s[col], bb1 = b2_s[col+1];
            float s0 = S[nt][0] + bb0, s1 = S[nt][1] + bb1;
            float s2 = S[nt][2] + bb0, s3 = S[nt][3] + bb1;
            if (diag) {
                const int jg = j0 + col;
                if (jg     > trow0) s0 = -1e30f;
                if (jg + 1 > trow0) s1 = -1e30f;
                if (jg     > trow1) s2 = -1e30f;
                if (jg + 1 > trow1) s3 = -1e30f;
            }
            const float p0 = __expf(s0), p1 = __expf(s1);
            const float p2 = __expf(s2), p3 = __expf(s3);
            rs0 += p0 + p1; rs1 += p2 + p3;
            __nv_bfloat162 h01 = __floats2bfloat162_rn(p0, p1);
            __nv_bfloat162 h23 = __floats2bfloat162_rn(p2, p3);
            __nv_bfloat162 l01 = __floats2bfloat162_rn(p0 - __bfloat162float(h01.x),
                                                       p1 - __bfloat162float(h01.y));
            __nv_bfloat162 l23 = __floats2bfloat162_rn(p2 - __bfloat162float(h23.x),
                                                       p3 - __bfloat162float(h23.y));
            const int ks = nt >> 1, half = (nt & 1) << 1;
            ph[ks][half]     = *(uint32_t*)&h01;           // row g
            ph[ks][half + 1] = *(uint32_t*)&h23;           // row g+8
            pl[ks][half]     = *(uint32_t*)&l01;
            pl[ks][half + 1] = *(uint32_t*)&l23;
        }

        // ---- O += (Ph+Pl) @ (Vth+Vtl)^T ----
        // 2-np batches, TERM-MAJOR inside each batch: same-O distance = 4.
        #pragma unroll
        for (int ks = 0; ks < 4; ks++) {
            #pragma unroll
            for (int nb = 0; nb < 2; nb++) {
                uint32_t bh[2][4], bl[2][4];
                #pragma unroll
                for (int i = 0; i < 2; i++) {
                    const int np = 2*nb + i;
                    const uint32_t ro = b_off + (uint32_t)(np * 16 * ASP * 2 + ks * 32);
                    LDSM_X4(bh[i], vth_b + ro);
                    LDSM_X4(bl[i], vtl_b + ro);
                }
                #pragma unroll
                for (int i = 0; i < 2; i++) {   // term 1: ph * vh
                    const int np = 2*nb + i;
                    uint32_t c0[2] = {bh[i][0], bh[i][1]}, c1[2] = {bh[i][2], bh[i][3]};
                    mma_bf16(O[2*np],   ph[ks], c0);
                    mma_bf16(O[2*np+1], ph[ks], c1);
                }
                #pragma unroll
                for (int i = 0; i < 2; i++) {   // term 2: ph * vl
                    const int np = 2*nb + i;
                    uint32_t c0[2] = {bl[i][0], bl[i][1]}, c1[2] = {bl[i][2], bl[i][3]};
                    mma_bf16(O[2*np],   ph[ks], c0);
                    mma_bf16(O[2*np+1], ph[ks], c1);
                }
                #pragma unroll
                for (int i = 0; i < 2; i++) {   // term 3: pl * vh
                    const int np = 2*nb + i;
                    uint32_t c0[2] = {bh[i][0], bh[i][1]}, c1[2] = {bh[i][2], bh[i][3]};
                    mma_bf16(O[2*np],   pl[ks], c0);
                    mma_bf16(O[2*np+1], pl[ks], c1);
                }
            }
        }
    }

    // quad-reduce row sums, normalize, store
    rs0 += __shfl_xor_sync(0xffffffffu, rs0, 1);
    rs0 += __shfl_xor_sync(0xffffffffu, rs0, 2);
    rs1 += __shfl_xor_sync(0xffffffffu, rs1, 1);
    rs1 += __shfl_xor_sync(0xffffffffu, rs1, 2);
    const float i0 = 1.f / rs0, i1 = 1.f / rs1;
    float* Ybase = Y + ((size_t)b * T_ + t0) * C_ + h * HSZ;
    #pragma unroll
    for (int nt = 0; nt < 8; nt++) {
        const int c = nt*8 + 2*t;
        *(float2*)(Ybase + (size_t)(wm + g) * C_ + c) =
            make_float2(O[nt][0] * i0, O[nt][1] * i0);
        *(float2*)(Ybase + (size_t)(wm + g + 8) * C_ + c) =
            make_float2(O[nt][2] * i1, O[nt][3] * i1);
    }
}

#define AT_SMEM ((128 + 3*64) * ASP * 2 + 64 * 4)   // 46336 B (x2 CTAs = 92.7KB)

// ---------------------------------------------------------------------------
extern "C" void kernel_launch(void* const* d_in, const int* in_sizes, int n_in,
                              void* d_out, int out_size)
{
    const float* x  = (const float*)d_in[0];
    const float* W1 = (const float*)d_in[1];
    const float* b1 = (const float*)d_in[2];
    const float* w2 = (const float*)d_in[3];
    const float* b2 = (const float*)d_in[4];
    const float* Wv = (const float*)d_in[5];
    const float* bv = (const float*)d_in[6];
    const float* Wp = (const float*)d_in[7];
    const float* bp = (const float*)d_in[8];
    float* out = (float*)d_out;

    float *Rp, *Vp, *Yp;
    cudaGetSymbolAddress((void**)&Rp, g_R);
    cudaGetSymbolAddress((void**)&Vp, g_V);
    cudaGetSymbolAddress((void**)&Yp, g_Y);

    const int M = B_ * T_;  // 4096
    dim3 gg(C_ / 128, M / 128);             // (8, 32)

    cudaFuncSetAttribute((const void*)gemm_hmma,
                         cudaFuncAttributeMaxDynamicSharedMemorySize, GT_SMEM);
    cudaFuncSetAttribute((const void*)synth_attn_tc,
                         cudaFuncAttributeMaxDynamicSharedMemorySize, AT_SMEM);

    gemm_hmma<<<gg, 256, GT_SMEM>>>(x, W1, b1, Rp, M, C_, C_, 1);   // R = relu(x W1^T + b1)
    gemm_hmma<<<gg, 256, GT_SMEM>>>(x, Wv, bv, Vp, M, C_, C_, 0);   // V = x Wv^T + bv

    dim3 ga(T_ / 128, NHEAD, B_);           // (16, 16, 2)
    synth_attn_tc<<<ga, 256, AT_SMEM>>>(Rp, Vp, w2, b2, Yp);

    gemm_hmma<<<gg, 256, GT_SMEM>>>(Yp, Wp, bp, out, M, C_, C_, 0); // out = Y Wp^T + bp
}